// round 1
// baseline (speedup 1.0000x reference)
#include <cuda_runtime.h>
#include <cstdint>
#include <cstddef>

// ---------------- static problem sizes (HTSAT stage-1 Swin block) ----------
#define B_IMG   64
#define HDIM    64
#define WDIM    64
#define WS      8
#define SS      4
#define NH      4
#define CDIM    96
#define HD      24           // head dim
#define NTOK    64           // tokens per window
#define NWIN    4096         // B_IMG * (64/8)*(64/8)
#define TOKENS  262144       // B_IMG * 4096
#define C3      288
#define CH      384          // 4*C

// ---------------- scratch (static device globals; no runtime alloc) --------
__device__ float g_hw [(size_t)TOKENS * CDIM];   // LN1 -> shifted windowed layout
__device__ float g_qkv[(size_t)TOKENS * C3];     // qkv projections
__device__ float g_o  [(size_t)TOKENS * CDIM];   // attention output (windowed)
__device__ float g_po [(size_t)TOKENS * CDIM];   // proj output (windowed)
__device__ float g_x1 [(size_t)TOKENS * CDIM];   // x + attn branch (token layout)
__device__ float g_h2 [(size_t)TOKENS * CDIM];   // LN2 output
__device__ float g_fc1[(size_t)TOKENS * CH];     // gelu(fc1)

// ---------------- LN1 + cyclic shift + window partition --------------------
// one warp per token; lane holds 3 channels
__global__ void ln1_shift_window(const float* __restrict__ x,
                                 const float* __restrict__ g,
                                 const float* __restrict__ b,
                                 float* __restrict__ out)
{
    int tok  = blockIdx.x * 4 + (threadIdx.x >> 5);
    int lane = threadIdx.x & 31;
    if (tok >= TOKENS) return;
    const float* xr = x + (size_t)tok * CDIM;
    float v0 = xr[lane*3+0], v1 = xr[lane*3+1], v2 = xr[lane*3+2];
    float s  = v0 + v1 + v2;
    float ss = v0*v0 + v1*v1 + v2*v2;
    #pragma unroll
    for (int o = 16; o; o >>= 1) {
        s  += __shfl_xor_sync(0xffffffffu, s,  o);
        ss += __shfl_xor_sync(0xffffffffu, ss, o);
    }
    float mu  = s * (1.0f/CDIM);
    float var = ss * (1.0f/CDIM) - mu*mu;
    float r   = rsqrtf(var + 1e-5f);

    // input coord (hi,wj) -> shifted coord i=(hi-SS)%64, j=(wj-SS)%64 -> window slot
    int bimg = tok >> 12;
    int hw   = tok & 4095;
    int hi   = hw >> 6, wj = hw & 63;
    int i = (hi + (HDIM - SS)) & (HDIM - 1);
    int j = (wj + (WDIM - SS)) & (WDIM - 1);
    int dtok = ((bimg * 64 + (i >> 3) * 8 + (j >> 3)) << 6) + ((i & 7) << 3) + (j & 7);
    float* orow = out + (size_t)dtok * CDIM;
    orow[lane*3+0] = (v0 - mu) * r * g[lane*3+0] + b[lane*3+0];
    orow[lane*3+1] = (v1 - mu) * r * g[lane*3+1] + b[lane*3+1];
    orow[lane*3+2] = (v2 - mu) * r * g[lane*3+2] + b[lane*3+2];
}

// ---------------- plain LN (token layout) -----------------------------------
__global__ void ln_plain(const float* __restrict__ x,
                         const float* __restrict__ g,
                         const float* __restrict__ b,
                         float* __restrict__ out)
{
    int tok  = blockIdx.x * 4 + (threadIdx.x >> 5);
    int lane = threadIdx.x & 31;
    if (tok >= TOKENS) return;
    const float* xr = x + (size_t)tok * CDIM;
    float v0 = xr[lane*3+0], v1 = xr[lane*3+1], v2 = xr[lane*3+2];
    float s  = v0 + v1 + v2;
    float ss = v0*v0 + v1*v1 + v2*v2;
    #pragma unroll
    for (int o = 16; o; o >>= 1) {
        s  += __shfl_xor_sync(0xffffffffu, s,  o);
        ss += __shfl_xor_sync(0xffffffffu, ss, o);
    }
    float mu  = s * (1.0f/CDIM);
    float var = ss * (1.0f/CDIM) - mu*mu;
    float r   = rsqrtf(var + 1e-5f);
    float* orow = out + (size_t)tok * CDIM;
    orow[lane*3+0] = (v0 - mu) * r * g[lane*3+0] + b[lane*3+0];
    orow[lane*3+1] = (v1 - mu) * r * g[lane*3+1] + b[lane*3+1];
    orow[lane*3+2] = (v2 - mu) * r * g[lane*3+2] + b[lane*3+2];
}

// ---------------- generic SGEMM: C[M,N] = A[M,K] @ W[N,K]^T + bias ----------
// act: 0 = none, 1 = exact GELU; res != nullptr -> add residual (same layout)
__global__ void sgemm_bias(const float* __restrict__ A,
                           const float* __restrict__ W,
                           const float* __restrict__ bias,
                           const float* __restrict__ res,
                           float* __restrict__ C,
                           int M, int N, int K, int act)
{
    const int BK = 16;
    __shared__ float As[BK][65];
    __shared__ float Bs[BK][65];
    int bm = blockIdx.y * 64;
    int bn = blockIdx.x * 64;
    int tid = threadIdx.x;
    int tm = (tid >> 4) * 4;   // 0..60
    int tn = (tid & 15) * 4;   // 0..60
    float acc[4][4] = {};

    for (int k0 = 0; k0 < K; k0 += BK) {
        #pragma unroll
        for (int i = tid; i < 64 * BK; i += 256) {
            int m = i >> 4, k = i & 15;
            As[k][m] = A[(size_t)(bm + m) * K + k0 + k];      // M always mult of 64
        }
        #pragma unroll
        for (int i = tid; i < 64 * BK; i += 256) {
            int n = i >> 4, k = i & 15;
            Bs[k][n] = (bn + n < N) ? W[(size_t)(bn + n) * K + k0 + k] : 0.0f;
        }
        __syncthreads();
        #pragma unroll
        for (int k = 0; k < BK; k++) {
            float a[4], bb[4];
            #pragma unroll
            for (int i = 0; i < 4; i++) a[i]  = As[k][tm + i];
            #pragma unroll
            for (int j = 0; j < 4; j++) bb[j] = Bs[k][tn + j];
            #pragma unroll
            for (int i = 0; i < 4; i++)
                #pragma unroll
                for (int j = 0; j < 4; j++)
                    acc[i][j] += a[i] * bb[j];
        }
        __syncthreads();
    }

    #pragma unroll
    for (int i = 0; i < 4; i++) {
        int m = bm + tm + i;
        #pragma unroll
        for (int j = 0; j < 4; j++) {
            int n = bn + tn + j;
            if (n >= N) continue;
            float v = acc[i][j] + bias[n];
            if (act == 1) v = 0.5f * v * (1.0f + erff(v * 0.70710678118654752f));
            if (res)      v += res[(size_t)m * N + n];
            C[(size_t)m * N + n] = v;
        }
    }
}

// ---------------- windowed attention ---------------------------------------
__device__ __forceinline__ int region3(int g) { return (g < 56) ? 0 : (g < 60 ? 1 : 2); }

__global__ void attn_kernel(const float* __restrict__ qkv,
                            const float* __restrict__ rpb,
                            float* __restrict__ o)
{
    int win  = blockIdx.x;          // 0..4095
    int head = blockIdx.y;          // 0..3
    int n    = threadIdx.x;         // 0..63 (query row)

    __shared__ float qs[NTOK][HD + 1];
    __shared__ float ks[NTOK][HD + 1];
    __shared__ float vs[NTOK][HD + 1];

    const float scale = 0.20412414523193150818f;  // 24^-0.5
    size_t base = (size_t)win * NTOK * C3;
    for (int i = n; i < NTOK * HD; i += NTOK) {
        int r = i / HD, d = i % HD;
        size_t ro = base + (size_t)r * C3 + head * HD + d;
        qs[r][d] = qkv[ro]           * scale;
        ks[r][d] = qkv[ro + CDIM];
        vs[r][d] = qkv[ro + 2*CDIM];
    }
    __syncthreads();

    int wimg = win & 63;
    int wi = wimg >> 3, wj = wimg & 7;
    int ni = n >> 3,    nj = n & 7;
    int rn = region3(wi*8 + ni) * 3 + region3(wj*8 + nj);

    float sc[NTOK];
    float mx = -1e30f;
    #pragma unroll
    for (int m = 0; m < NTOK; m++) {
        float s = 0.0f;
        #pragma unroll
        for (int d = 0; d < HD; d++) s += qs[n][d] * ks[m][d];
        int mi = m >> 3, mj = m & 7;
        int rm = region3(wi*8 + mi) * 3 + region3(wj*8 + mj);
        int ridx = (ni - mi + 7) * 15 + (nj - mj + 7);
        s += rpb[ridx * NH + head];
        if (rm != rn) s -= 100.0f;
        sc[m] = s;
        mx = fmaxf(mx, s);
    }
    float sum = 0.0f;
    #pragma unroll
    for (int m = 0; m < NTOK; m++) { sc[m] = __expf(sc[m] - mx); sum += sc[m]; }
    float inv = 1.0f / sum;

    float* orow = o + ((size_t)win * NTOK + n) * CDIM + head * HD;
    #pragma unroll
    for (int d = 0; d < HD; d++) {
        float acc = 0.0f;
        #pragma unroll
        for (int m = 0; m < NTOK; m++) acc += sc[m] * vs[m][d];
        orow[d] = acc * inv;
    }
}

// ---------------- window reverse + unshift + residual ----------------------
__global__ void reverse_residual(const float* __restrict__ x,
                                 const float* __restrict__ po,
                                 float* __restrict__ x1)
{
    size_t idx = (size_t)blockIdx.x * 256 + threadIdx.x;
    if (idx >= (size_t)TOKENS * CDIM) return;
    int c = idx % CDIM;
    size_t tok = idx / CDIM;
    int bimg = (int)(tok >> 12);
    int hw   = (int)(tok & 4095);
    int hi = hw >> 6, wj = hw & 63;
    int i = (hi + (HDIM - SS)) & (HDIM - 1);
    int j = (wj + (WDIM - SS)) & (WDIM - 1);
    int stok = ((bimg * 64 + (i >> 3) * 8 + (j >> 3)) << 6) + ((i & 7) << 3) + (j & 7);
    x1[idx] = x[idx] + po[(size_t)stok * CDIM + c];
}

// ---------------- launch ----------------------------------------------------
extern "C" void kernel_launch(void* const* d_in, const int* in_sizes, int n_in,
                              void* d_out, int out_size)
{
    const float* x       = (const float*)d_in[0];
    const float* norm1_g = (const float*)d_in[1];
    const float* norm1_b = (const float*)d_in[2];
    const float* qkv_w   = (const float*)d_in[3];
    const float* qkv_b   = (const float*)d_in[4];
    const float* rpb     = (const float*)d_in[5];
    const float* proj_w  = (const float*)d_in[6];
    const float* proj_b  = (const float*)d_in[7];
    const float* norm2_g = (const float*)d_in[8];
    const float* norm2_b = (const float*)d_in[9];
    const float* fc1_w   = (const float*)d_in[10];
    const float* fc1_b   = (const float*)d_in[11];
    const float* fc2_w   = (const float*)d_in[12];
    const float* fc2_b   = (const float*)d_in[13];
    float* out = (float*)d_out;

    float *hw_p, *qkv_p, *o_p, *po_p, *x1_p, *h2_p, *fc1_p;
    cudaGetSymbolAddress((void**)&hw_p,  g_hw);
    cudaGetSymbolAddress((void**)&qkv_p, g_qkv);
    cudaGetSymbolAddress((void**)&o_p,   g_o);
    cudaGetSymbolAddress((void**)&po_p,  g_po);
    cudaGetSymbolAddress((void**)&x1_p,  g_x1);
    cudaGetSymbolAddress((void**)&h2_p,  g_h2);
    cudaGetSymbolAddress((void**)&fc1_p, g_fc1);

    // 1) LN1 + shift + window partition
    ln1_shift_window<<<TOKENS/4, 128>>>(x, norm1_g, norm1_b, hw_p);

    // 2) QKV GEMM: (262144 x 96) @ (288 x 96)^T
    {
        dim3 grid((C3 + 63) / 64, TOKENS / 64);
        sgemm_bias<<<grid, 256>>>(hw_p, qkv_w, qkv_b, nullptr, qkv_p,
                                  TOKENS, C3, CDIM, 0);
    }

    // 3) windowed attention
    {
        dim3 grid(NWIN, NH);
        attn_kernel<<<grid, NTOK>>>(qkv_p, rpb, o_p);
    }

    // 4) proj GEMM: (262144 x 96) @ (96 x 96)^T
    {
        dim3 grid((CDIM + 63) / 64, TOKENS / 64);
        sgemm_bias<<<grid, 256>>>(o_p, proj_w, proj_b, nullptr, po_p,
                                  TOKENS, CDIM, CDIM, 0);
    }

    // 5) window reverse + unshift + residual -> x1
    {
        size_t total = (size_t)TOKENS * CDIM;
        reverse_residual<<<(unsigned)((total + 255) / 256), 256>>>(x, po_p, x1_p);
    }

    // 6) LN2
    ln_plain<<<TOKENS/4, 128>>>(x1_p, norm2_g, norm2_b, h2_p);

    // 7) FC1 + GELU: (262144 x 96) @ (384 x 96)^T
    {
        dim3 grid((CH + 63) / 64, TOKENS / 64);
        sgemm_bias<<<grid, 256>>>(h2_p, fc1_w, fc1_b, nullptr, fc1_p,
                                  TOKENS, CH, CDIM, 1);
    }

    // 8) FC2 + residual: (262144 x 384) @ (96 x 384)^T + x1 -> out
    {
        dim3 grid((CDIM + 63) / 64, TOKENS / 64);
        sgemm_bias<<<grid, 256>>>(fc1_p, fc2_w, fc2_b, x1_p, out,
                                  TOKENS, CDIM, CH, 0);
    }
}

// round 2
// speedup vs baseline: 2.2613x; 2.2613x over previous
#include <cuda_runtime.h>
#include <cstdint>
#include <cstddef>

// ---------------- static problem sizes (HTSAT stage-1 Swin block) ----------
#define B_IMG   64
#define HDIM    64
#define WDIM    64
#define WS      8
#define SS      4
#define NH      4
#define CDIM    96
#define HD      24
#define NTOK    64
#define NWIN    4096
#define TOKENS  262144
#define C3      288
#define CH      384

// ---------------- scratch ---------------------------------------------------
__device__ float g_hw [(size_t)TOKENS * CDIM];
__device__ float g_qkv[(size_t)TOKENS * C3];
__device__ float g_o  [(size_t)TOKENS * CDIM];
__device__ float g_po [(size_t)TOKENS * CDIM];
__device__ float g_x1 [(size_t)TOKENS * CDIM];
__device__ float g_h2 [(size_t)TOKENS * CDIM];
__device__ float g_fc1[(size_t)TOKENS * CH];

// ---------------- helpers ----------------------------------------------------
__device__ __forceinline__ uint32_t f2tf(float f) {
    uint32_t u;
    asm("cvt.rna.tf32.f32 %0, %1;" : "=r"(u) : "f"(f));
    return u;
}

__device__ __forceinline__ void mma_tf32(float c[4],
                                         const uint32_t a[4],
                                         const uint32_t b[2]) {
    asm volatile(
        "mma.sync.aligned.m16n8k8.row.col.f32.tf32.tf32.f32 "
        "{%0,%1,%2,%3}, {%4,%5,%6,%7}, {%8,%9}, {%0,%1,%2,%3};\n"
        : "+f"(c[0]), "+f"(c[1]), "+f"(c[2]), "+f"(c[3])
        : "r"(a[0]), "r"(a[1]), "r"(a[2]), "r"(a[3]),
          "r"(b[0]), "r"(b[1]));
}

// ---------------- LN1 + cyclic shift + window partition --------------------
__global__ void ln1_shift_window(const float* __restrict__ x,
                                 const float* __restrict__ g,
                                 const float* __restrict__ b,
                                 float* __restrict__ out)
{
    int tok  = blockIdx.x * 4 + (threadIdx.x >> 5);
    int lane = threadIdx.x & 31;
    if (tok >= TOKENS) return;
    const float* xr = x + (size_t)tok * CDIM;
    float v0 = xr[lane*3+0], v1 = xr[lane*3+1], v2 = xr[lane*3+2];
    float s  = v0 + v1 + v2;
    float ss = v0*v0 + v1*v1 + v2*v2;
    #pragma unroll
    for (int o = 16; o; o >>= 1) {
        s  += __shfl_xor_sync(0xffffffffu, s,  o);
        ss += __shfl_xor_sync(0xffffffffu, ss, o);
    }
    float mu  = s * (1.0f/CDIM);
    float var = ss * (1.0f/CDIM) - mu*mu;
    float r   = rsqrtf(var + 1e-5f);

    int bimg = tok >> 12;
    int hw   = tok & 4095;
    int hi   = hw >> 6, wj = hw & 63;
    int i = (hi + (HDIM - SS)) & (HDIM - 1);
    int j = (wj + (WDIM - SS)) & (WDIM - 1);
    int dtok = ((bimg * 64 + (i >> 3) * 8 + (j >> 3)) << 6) + ((i & 7) << 3) + (j & 7);
    float* orow = out + (size_t)dtok * CDIM;
    orow[lane*3+0] = (v0 - mu) * r * g[lane*3+0] + b[lane*3+0];
    orow[lane*3+1] = (v1 - mu) * r * g[lane*3+1] + b[lane*3+1];
    orow[lane*3+2] = (v2 - mu) * r * g[lane*3+2] + b[lane*3+2];
}

// ---------------- plain LN ---------------------------------------------------
__global__ void ln_plain(const float* __restrict__ x,
                         const float* __restrict__ g,
                         const float* __restrict__ b,
                         float* __restrict__ out)
{
    int tok  = blockIdx.x * 4 + (threadIdx.x >> 5);
    int lane = threadIdx.x & 31;
    if (tok >= TOKENS) return;
    const float* xr = x + (size_t)tok * CDIM;
    float v0 = xr[lane*3+0], v1 = xr[lane*3+1], v2 = xr[lane*3+2];
    float s  = v0 + v1 + v2;
    float ss = v0*v0 + v1*v1 + v2*v2;
    #pragma unroll
    for (int o = 16; o; o >>= 1) {
        s  += __shfl_xor_sync(0xffffffffu, s,  o);
        ss += __shfl_xor_sync(0xffffffffu, ss, o);
    }
    float mu  = s * (1.0f/CDIM);
    float var = ss * (1.0f/CDIM) - mu*mu;
    float r   = rsqrtf(var + 1e-5f);
    float* orow = out + (size_t)tok * CDIM;
    orow[lane*3+0] = (v0 - mu) * r * g[lane*3+0] + b[lane*3+0];
    orow[lane*3+1] = (v1 - mu) * r * g[lane*3+1] + b[lane*3+1];
    orow[lane*3+2] = (v2 - mu) * r * g[lane*3+2] + b[lane*3+2];
}

// ---------------- TF32 tensor-core GEMM: C[M,N] = A[M,K] @ W[N,K]^T ---------
// BM=128, BN=96, BK=32. 8 warps, warp tile 32x48 (2 x 6 m16n8k8 tiles).
// N must be a multiple of 96; K a multiple of 32; M a multiple of 128.
// act: 0 none, 1 exact GELU. res != nullptr -> add residual.
__global__ void __launch_bounds__(256)
gemm_tf32(const float* __restrict__ A,
          const float* __restrict__ W,
          const float* __restrict__ bias,
          const float* __restrict__ res,
          float* __restrict__ C,
          int M, int N, int K, int act)
{
    __shared__ uint32_t As[32][132];   // [k][m], pad 4 -> 2-way max conflicts
    __shared__ uint32_t Bs[32][100];   // [k][n], pad 4

    const int t    = threadIdx.x;
    const int bm   = blockIdx.y * 128;
    const int bn   = blockIdx.x * 96;
    const int warp = t >> 5, lane = t & 31;
    const int wrow = warp & 3;         // 4 warps along M
    const int wcol = warp >> 2;        // 2 warps along N
    const int gid  = lane >> 2, tig = lane & 3;

    const int lm = t >> 3;             // 0..31
    const int lk = (t & 7) * 4;        // 0,4,..,28

    float acc[2][6][4];
    #pragma unroll
    for (int i = 0; i < 2; i++)
        #pragma unroll
        for (int j = 0; j < 6; j++)
            #pragma unroll
            for (int q = 0; q < 4; q++) acc[i][j][q] = 0.0f;

    for (int k0 = 0; k0 < K; k0 += 32) {
        // stage A tile (128 x 32)
        #pragma unroll
        for (int i = 0; i < 4; i++) {
            const float4 v = *(const float4*)&A[(size_t)(bm + lm + 32*i) * K + k0 + lk];
            As[lk+0][lm + 32*i] = f2tf(v.x);
            As[lk+1][lm + 32*i] = f2tf(v.y);
            As[lk+2][lm + 32*i] = f2tf(v.z);
            As[lk+3][lm + 32*i] = f2tf(v.w);
        }
        // stage B tile (96 x 32)
        #pragma unroll
        for (int i = 0; i < 3; i++) {
            const float4 v = *(const float4*)&W[(size_t)(bn + lm + 32*i) * K + k0 + lk];
            Bs[lk+0][lm + 32*i] = f2tf(v.x);
            Bs[lk+1][lm + 32*i] = f2tf(v.y);
            Bs[lk+2][lm + 32*i] = f2tf(v.z);
            Bs[lk+3][lm + 32*i] = f2tf(v.w);
        }
        __syncthreads();

        #pragma unroll
        for (int ks = 0; ks < 32; ks += 8) {
            uint32_t af[2][4];
            #pragma unroll
            for (int mt = 0; mt < 2; mt++) {
                const int mb = wrow*32 + mt*16;
                af[mt][0] = As[ks + tig    ][mb + gid    ];
                af[mt][1] = As[ks + tig    ][mb + gid + 8];
                af[mt][2] = As[ks + tig + 4][mb + gid    ];
                af[mt][3] = As[ks + tig + 4][mb + gid + 8];
            }
            uint32_t bf[6][2];
            #pragma unroll
            for (int nt = 0; nt < 6; nt++) {
                const int nb = wcol*48 + nt*8;
                bf[nt][0] = Bs[ks + tig    ][nb + gid];
                bf[nt][1] = Bs[ks + tig + 4][nb + gid];
            }
            #pragma unroll
            for (int mt = 0; mt < 2; mt++)
                #pragma unroll
                for (int nt = 0; nt < 6; nt++)
                    mma_tf32(acc[mt][nt], af[mt], bf[nt]);
        }
        __syncthreads();
    }

    // epilogue
    #pragma unroll
    for (int mt = 0; mt < 2; mt++) {
        const int r0 = bm + wrow*32 + mt*16 + gid;
        const int r1 = r0 + 8;
        #pragma unroll
        for (int nt = 0; nt < 6; nt++) {
            const int col = bn + wcol*48 + nt*8 + tig*2;
            const float b0 = bias[col], b1 = bias[col+1];
            float v00 = acc[mt][nt][0] + b0;
            float v01 = acc[mt][nt][1] + b1;
            float v10 = acc[mt][nt][2] + b0;
            float v11 = acc[mt][nt][3] + b1;
            if (act == 1) {
                v00 = 0.5f * v00 * (1.0f + erff(v00 * 0.70710678118654752f));
                v01 = 0.5f * v01 * (1.0f + erff(v01 * 0.70710678118654752f));
                v10 = 0.5f * v10 * (1.0f + erff(v10 * 0.70710678118654752f));
                v11 = 0.5f * v11 * (1.0f + erff(v11 * 0.70710678118654752f));
            }
            if (res) {
                v00 += res[(size_t)r0 * N + col];
                v01 += res[(size_t)r0 * N + col + 1];
                v10 += res[(size_t)r1 * N + col];
                v11 += res[(size_t)r1 * N + col + 1];
            }
            *(float2*)&C[(size_t)r0 * N + col] = make_float2(v00, v01);
            *(float2*)&C[(size_t)r1 * N + col] = make_float2(v10, v11);
        }
    }
}

// ---------------- windowed attention ---------------------------------------
__device__ __forceinline__ int region3(int g) { return (g < 56) ? 0 : (g < 60 ? 1 : 2); }

__global__ void attn_kernel(const float* __restrict__ qkv,
                            const float* __restrict__ rpb,
                            float* __restrict__ o)
{
    int win  = blockIdx.x;
    int head = blockIdx.y;
    int n    = threadIdx.x;

    __shared__ float qs[NTOK][HD + 1];
    __shared__ float ks[NTOK][HD + 1];
    __shared__ float vs[NTOK][HD + 1];

    const float scale = 0.20412414523193150818f;
    size_t base = (size_t)win * NTOK * C3;
    for (int i = n; i < NTOK * HD; i += NTOK) {
        int r = i / HD, d = i % HD;
        size_t ro = base + (size_t)r * C3 + head * HD + d;
        qs[r][d] = qkv[ro] * scale;
        ks[r][d] = qkv[ro + CDIM];
        vs[r][d] = qkv[ro + 2*CDIM];
    }
    __syncthreads();

    float qr[HD];
    #pragma unroll
    for (int d = 0; d < HD; d++) qr[d] = qs[n][d];

    int wimg = win & 63;
    int wi = wimg >> 3, wj = wimg & 7;
    int ni = n >> 3,    nj = n & 7;
    int rn = region3(wi*8 + ni) * 3 + region3(wj*8 + nj);

    float sc[NTOK];
    float mx = -1e30f;
    #pragma unroll
    for (int m = 0; m < NTOK; m++) {
        float s = 0.0f;
        #pragma unroll
        for (int d = 0; d < HD; d++) s += qr[d] * ks[m][d];
        int mi = m >> 3, mj = m & 7;
        int rm = region3(wi*8 + mi) * 3 + region3(wj*8 + mj);
        int ridx = (ni - mi + 7) * 15 + (nj - mj + 7);
        s += rpb[ridx * NH + head];
        if (rm != rn) s -= 100.0f;
        sc[m] = s;
        mx = fmaxf(mx, s);
    }
    float sum = 0.0f;
    #pragma unroll
    for (int m = 0; m < NTOK; m++) { sc[m] = __expf(sc[m] - mx); sum += sc[m]; }
    float inv = 1.0f / sum;

    float* orow = o + ((size_t)win * NTOK + n) * CDIM + head * HD;
    #pragma unroll
    for (int d = 0; d < HD; d++) {
        float accv = 0.0f;
        #pragma unroll
        for (int m = 0; m < NTOK; m++) accv += sc[m] * vs[m][d];
        orow[d] = accv * inv;
    }
}

// ---------------- window reverse + unshift + residual ----------------------
__global__ void reverse_residual(const float* __restrict__ x,
                                 const float* __restrict__ po,
                                 float* __restrict__ x1)
{
    size_t idx = (size_t)blockIdx.x * 256 + threadIdx.x;
    if (idx >= (size_t)TOKENS * CDIM) return;
    int c = idx % CDIM;
    size_t tok = idx / CDIM;
    int bimg = (int)(tok >> 12);
    int hw   = (int)(tok & 4095);
    int hi = hw >> 6, wj = hw & 63;
    int i = (hi + (HDIM - SS)) & (HDIM - 1);
    int j = (wj + (WDIM - SS)) & (WDIM - 1);
    int stok = ((bimg * 64 + (i >> 3) * 8 + (j >> 3)) << 6) + ((i & 7) << 3) + (j & 7);
    x1[idx] = x[idx] + po[(size_t)stok * CDIM + c];
}

// ---------------- launch ----------------------------------------------------
extern "C" void kernel_launch(void* const* d_in, const int* in_sizes, int n_in,
                              void* d_out, int out_size)
{
    const float* x       = (const float*)d_in[0];
    const float* norm1_g = (const float*)d_in[1];
    const float* norm1_b = (const float*)d_in[2];
    const float* qkv_w   = (const float*)d_in[3];
    const float* qkv_b   = (const float*)d_in[4];
    const float* rpb     = (const float*)d_in[5];
    const float* proj_w  = (const float*)d_in[6];
    const float* proj_b  = (const float*)d_in[7];
    const float* norm2_g = (const float*)d_in[8];
    const float* norm2_b = (const float*)d_in[9];
    const float* fc1_w   = (const float*)d_in[10];
    const float* fc1_b   = (const float*)d_in[11];
    const float* fc2_w   = (const float*)d_in[12];
    const float* fc2_b   = (const float*)d_in[13];
    float* out = (float*)d_out;

    float *hw_p, *qkv_p, *o_p, *po_p, *x1_p, *h2_p, *fc1_p;
    cudaGetSymbolAddress((void**)&hw_p,  g_hw);
    cudaGetSymbolAddress((void**)&qkv_p, g_qkv);
    cudaGetSymbolAddress((void**)&o_p,   g_o);
    cudaGetSymbolAddress((void**)&po_p,  g_po);
    cudaGetSymbolAddress((void**)&x1_p,  g_x1);
    cudaGetSymbolAddress((void**)&h2_p,  g_h2);
    cudaGetSymbolAddress((void**)&fc1_p, g_fc1);

    // 1) LN1 + shift + window partition
    ln1_shift_window<<<TOKENS/4, 128>>>(x, norm1_g, norm1_b, hw_p);

    // 2) QKV GEMM
    gemm_tf32<<<dim3(C3/96, TOKENS/128), 256>>>(hw_p, qkv_w, qkv_b, nullptr, qkv_p,
                                                TOKENS, C3, CDIM, 0);

    // 3) windowed attention
    attn_kernel<<<dim3(NWIN, NH), NTOK>>>(qkv_p, rpb, o_p);

    // 4) proj GEMM
    gemm_tf32<<<dim3(CDIM/96, TOKENS/128), 256>>>(o_p, proj_w, proj_b, nullptr, po_p,
                                                  TOKENS, CDIM, CDIM, 0);

    // 5) window reverse + unshift + residual
    {
        size_t total = (size_t)TOKENS * CDIM;
        reverse_residual<<<(unsigned)((total + 255) / 256), 256>>>(x, po_p, x1_p);
    }

    // 6) LN2
    ln_plain<<<TOKENS/4, 128>>>(x1_p, norm2_g, norm2_b, h2_p);

    // 7) FC1 + GELU
    gemm_tf32<<<dim3(CH/96, TOKENS/128), 256>>>(h2_p, fc1_w, fc1_b, nullptr, fc1_p,
                                                TOKENS, CH, CDIM, 1);

    // 8) FC2 + residual
    gemm_tf32<<<dim3(CDIM/96, TOKENS/128), 256>>>(fc1_p, fc2_w, fc2_b, x1_p, out,
                                                  TOKENS, CDIM, CH, 0);
}

// round 3
// speedup vs baseline: 3.1824x; 1.4074x over previous
#include <cuda_runtime.h>
#include <cuda_bf16.h>
#include <cstdint>
#include <cstddef>

// ---------------- static problem sizes -------------------------------------
#define B_IMG   64
#define HDIM    64
#define WDIM    64
#define WS      8
#define SS      4
#define NH      4
#define CDIM    96
#define HD      24
#define NTOK    64
#define NWIN    4096
#define TOKENS  262144
#define C3      288
#define CH      384

typedef __nv_bfloat16 bf16;

// ---------------- scratch ---------------------------------------------------
__device__ bf16  g_hw [(size_t)TOKENS * CDIM];
__device__ bf16  g_qkv[(size_t)TOKENS * C3];
__device__ bf16  g_o  [(size_t)TOKENS * CDIM];
__device__ float g_x1 [(size_t)TOKENS * CDIM];
__device__ bf16  g_h2 [(size_t)TOKENS * CDIM];
__device__ bf16  g_fc1[(size_t)TOKENS * CH];
__device__ bf16  g_wqkv[C3 * CDIM];
__device__ bf16  g_wproj[CDIM * CDIM];
__device__ bf16  g_wfc1[CH * CDIM];
__device__ bf16  g_wfc2[CDIM * CH];

// ---------------- asm helpers ----------------------------------------------
__device__ __forceinline__ void ldm_x4(uint32_t& r0, uint32_t& r1, uint32_t& r2,
                                       uint32_t& r3, uint32_t addr) {
    asm volatile("ldmatrix.sync.aligned.m8n8.x4.shared.b16 {%0,%1,%2,%3}, [%4];\n"
                 : "=r"(r0), "=r"(r1), "=r"(r2), "=r"(r3) : "r"(addr));
}
__device__ __forceinline__ void mma_bf16(float c[4], const uint32_t a[4],
                                         const uint32_t b[2]) {
    asm volatile(
        "mma.sync.aligned.m16n8k16.row.col.f32.bf16.bf16.f32 "
        "{%0,%1,%2,%3},{%4,%5,%6,%7},{%8,%9},{%0,%1,%2,%3};\n"
        : "+f"(c[0]), "+f"(c[1]), "+f"(c[2]), "+f"(c[3])
        : "r"(a[0]), "r"(a[1]), "r"(a[2]), "r"(a[3]), "r"(b[0]), "r"(b[1]));
}
__device__ __forceinline__ void cp16(uint32_t dst, const void* src) {
    asm volatile("cp.async.ca.shared.global [%0], [%1], 16;\n"
                 :: "r"(dst), "l"(src));
}
__device__ __forceinline__ void cp_commit() { asm volatile("cp.async.commit_group;\n"); }
__device__ __forceinline__ void cp_wait_all() { asm volatile("cp.async.wait_group 0;\n"); }

// ---------------- weight conversion -----------------------------------------
__global__ void conv_weights(const float* __restrict__ a, const float* __restrict__ b,
                             const float* __restrict__ c, const float* __restrict__ d)
{
    int i = blockIdx.x * 256 + threadIdx.x;
    if (i < C3 * CDIM)   g_wqkv[i]  = __float2bfloat16(a[i]);
    if (i < CDIM * CDIM) g_wproj[i] = __float2bfloat16(b[i]);
    if (i < CH * CDIM) { g_wfc1[i]  = __float2bfloat16(c[i]);
                         g_wfc2[i]  = __float2bfloat16(d[i]); }
}

// ---------------- LN1 + shift + window partition (bf16 out) ----------------
__global__ void ln1_shift_window(const float* __restrict__ x,
                                 const float* __restrict__ g,
                                 const float* __restrict__ b,
                                 bf16* __restrict__ out)
{
    int tok  = blockIdx.x * 4 + (threadIdx.x >> 5);
    int lane = threadIdx.x & 31;
    const float* xr = x + (size_t)tok * CDIM;
    float v0 = xr[lane*3+0], v1 = xr[lane*3+1], v2 = xr[lane*3+2];
    float s  = v0 + v1 + v2;
    float ss = v0*v0 + v1*v1 + v2*v2;
    #pragma unroll
    for (int o = 16; o; o >>= 1) {
        s  += __shfl_xor_sync(0xffffffffu, s,  o);
        ss += __shfl_xor_sync(0xffffffffu, ss, o);
    }
    float mu  = s * (1.0f/CDIM);
    float var = ss * (1.0f/CDIM) - mu*mu;
    float r   = rsqrtf(var + 1e-5f);

    int bimg = tok >> 12;
    int hw   = tok & 4095;
    int hi   = hw >> 6, wj = hw & 63;
    int i = (hi + (HDIM - SS)) & (HDIM - 1);
    int j = (wj + (WDIM - SS)) & (WDIM - 1);
    int dtok = ((bimg * 64 + (i >> 3) * 8 + (j >> 3)) << 6) + ((i & 7) << 3) + (j & 7);
    bf16* orow = out + (size_t)dtok * CDIM;
    orow[lane*3+0] = __float2bfloat16((v0 - mu) * r * g[lane*3+0] + b[lane*3+0]);
    orow[lane*3+1] = __float2bfloat16((v1 - mu) * r * g[lane*3+1] + b[lane*3+1]);
    orow[lane*3+2] = __float2bfloat16((v2 - mu) * r * g[lane*3+2] + b[lane*3+2]);
}

// ---------------- plain LN (bf16 out) ---------------------------------------
__global__ void ln_plain(const float* __restrict__ x,
                         const float* __restrict__ g,
                         const float* __restrict__ b,
                         bf16* __restrict__ out)
{
    int tok  = blockIdx.x * 4 + (threadIdx.x >> 5);
    int lane = threadIdx.x & 31;
    const float* xr = x + (size_t)tok * CDIM;
    float v0 = xr[lane*3+0], v1 = xr[lane*3+1], v2 = xr[lane*3+2];
    float s  = v0 + v1 + v2;
    float ss = v0*v0 + v1*v1 + v2*v2;
    #pragma unroll
    for (int o = 16; o; o >>= 1) {
        s  += __shfl_xor_sync(0xffffffffu, s,  o);
        ss += __shfl_xor_sync(0xffffffffu, ss, o);
    }
    float mu  = s * (1.0f/CDIM);
    float var = ss * (1.0f/CDIM) - mu*mu;
    float r   = rsqrtf(var + 1e-5f);
    bf16* orow = out + (size_t)tok * CDIM;
    orow[lane*3+0] = __float2bfloat16((v0 - mu) * r * g[lane*3+0] + b[lane*3+0]);
    orow[lane*3+1] = __float2bfloat16((v1 - mu) * r * g[lane*3+1] + b[lane*3+1]);
    orow[lane*3+2] = __float2bfloat16((v2 - mu) * r * g[lane*3+2] + b[lane*3+2]);
}

// ---------------- bf16 tensor-core GEMM -------------------------------------
// C[M,N] = A[M,K] @ W[N,K]^T + bias.  BM=128, BN=96, BK=32, 8 warps (4x2),
// warp tile 32x48 (2x6 m16n8k16).  MODE: 0=QKV(bf16 out), 1=PROJ(scatter+x res,
// f32 out), 2=FC1(gelu, bf16 out), 3=FC2(+x1 res, f32 out).
#define SROW 40   // smem row stride in elements (80B: 16B-aligned, ldmatrix conflict-free)

template<int MODE>
__global__ void __launch_bounds__(256)
gemm_bf16(const bf16* __restrict__ A, const bf16* __restrict__ W,
          const float* __restrict__ bias, const float* __restrict__ aux,
          void* __restrict__ Cout, int K, int N)
{
    __shared__ bf16 As[2][128][SROW];
    __shared__ bf16 Bs[2][96][SROW];

    const int t    = threadIdx.x;
    const int bm   = blockIdx.y * 128;
    const int bn   = blockIdx.x * 96;
    const int warp = t >> 5, lane = t & 31;
    const int wrow = warp & 3;
    const int wcol = warp >> 2;
    const int gid  = lane >> 2, tig = lane & 3;

    float acc[2][6][4];
    #pragma unroll
    for (int i = 0; i < 2; i++)
        #pragma unroll
        for (int j = 0; j < 6; j++)
            #pragma unroll
            for (int q = 0; q < 4; q++) acc[i][j][q] = 0.0f;

    const int nk = K >> 5;

    // staging indices
    const int a_row = t >> 1;              // with two chunks per thread
    auto issue = [&](int kt, int buf) {
        const int k0 = kt << 5;
        #pragma unroll
        for (int c = 0; c < 2; c++) {
            int cid = t + c * 256;          // 0..511
            int row = cid >> 2, cc = cid & 3;
            uint32_t dst = (uint32_t)__cvta_generic_to_shared(&As[buf][row][cc * 8]);
            cp16(dst, A + (size_t)(bm + row) * K + k0 + cc * 8);
        }
        {
            int row = t >> 2, cc = t & 3;
            uint32_t dst = (uint32_t)__cvta_generic_to_shared(&Bs[buf][row][cc * 8]);
            cp16(dst, W + (size_t)(bn + row) * K + k0 + cc * 8);
        }
        if (t < 128) {
            int cid = 256 + t;
            int row = cid >> 2, cc = cid & 3;
            uint32_t dst = (uint32_t)__cvta_generic_to_shared(&Bs[buf][row][cc * 8]);
            cp16(dst, W + (size_t)(bn + row) * K + k0 + cc * 8);
        }
        cp_commit();
    };
    (void)a_row;

    issue(0, 0);

    for (int kt = 0; kt < nk; kt++) {
        cp_wait_all();
        __syncthreads();
        if (kt + 1 < nk) issue(kt + 1, (kt + 1) & 1);
        const int buf = kt & 1;

        #pragma unroll
        for (int ks = 0; ks < 32; ks += 16) {
            // A fragments
            uint32_t af[2][4];
            #pragma unroll
            for (int mt = 0; mt < 2; mt++) {
                int row = wrow * 32 + mt * 16 + (lane & 15);
                int col = ks + ((lane >> 4) << 3);
                uint32_t addr = (uint32_t)__cvta_generic_to_shared(&As[buf][row][col]);
                ldm_x4(af[mt][0], af[mt][1], af[mt][2], af[mt][3], addr);
            }
            // B fragments: 3 x4 loads -> 6 n-tiles
            uint32_t bf[6][2];
            #pragma unroll
            for (int pr = 0; pr < 3; pr++) {
                int row = wcol * 48 + pr * 16 + (lane & 7) + ((lane >> 4) << 3);
                int col = ks + (((lane >> 3) & 1) << 3);
                uint32_t addr = (uint32_t)__cvta_generic_to_shared(&Bs[buf][row][col]);
                uint32_t r0, r1, r2, r3;
                ldm_x4(r0, r1, r2, r3, addr);
                bf[pr*2  ][0] = r0; bf[pr*2  ][1] = r1;
                bf[pr*2+1][0] = r2; bf[pr*2+1][1] = r3;
            }
            #pragma unroll
            for (int mt = 0; mt < 2; mt++)
                #pragma unroll
                for (int nt = 0; nt < 6; nt++)
                    mma_bf16(acc[mt][nt], af[mt], bf[nt]);
        }
        __syncthreads();
    }

    // ---------------- epilogue ----------------
    #pragma unroll
    for (int mt = 0; mt < 2; mt++) {
        const int r0 = bm + wrow * 32 + mt * 16 + gid;
        const int r1 = r0 + 8;
        int d0 = r0, d1 = r1;
        if (MODE == 1) {
            // inverse shift+window map: stok -> token index
            int w0 = (r0 >> 6) & 63, s0 = r0 & 63;
            int i0 = ((w0 >> 3) << 3) + (s0 >> 3), j0 = ((w0 & 7) << 3) + (s0 & 7);
            d0 = (r0 & ~4095) | ((((i0 + SS) & 63) << 6) | ((j0 + SS) & 63));
            int w1 = (r1 >> 6) & 63, s1 = r1 & 63;
            int i1 = ((w1 >> 3) << 3) + (s1 >> 3), j1 = ((w1 & 7) << 3) + (s1 & 7);
            d1 = (r1 & ~4095) | ((((i1 + SS) & 63) << 6) | ((j1 + SS) & 63));
        }
        #pragma unroll
        for (int nt = 0; nt < 6; nt++) {
            const int col = bn + wcol * 48 + nt * 8 + tig * 2;
            const float b0 = bias[col], b1 = bias[col + 1];
            float v00 = acc[mt][nt][0] + b0;
            float v01 = acc[mt][nt][1] + b1;
            float v10 = acc[mt][nt][2] + b0;
            float v11 = acc[mt][nt][3] + b1;
            if (MODE == 0) {
                bf16* C = (bf16*)Cout;
                *(__nv_bfloat162*)&C[(size_t)r0 * N + col] =
                    __nv_bfloat162(__float2bfloat16(v00), __float2bfloat16(v01));
                *(__nv_bfloat162*)&C[(size_t)r1 * N + col] =
                    __nv_bfloat162(__float2bfloat16(v10), __float2bfloat16(v11));
            } else if (MODE == 1) {
                float* C = (float*)Cout;
                size_t o0 = (size_t)d0 * CDIM + col;
                size_t o1 = (size_t)d1 * CDIM + col;
                float2 x0 = *(const float2*)&aux[o0];
                float2 x1v = *(const float2*)&aux[o1];
                *(float2*)&C[o0] = make_float2(v00 + x0.x,  v01 + x0.y);
                *(float2*)&C[o1] = make_float2(v10 + x1v.x, v11 + x1v.y);
            } else if (MODE == 2) {
                v00 = 0.5f * v00 * (1.0f + erff(v00 * 0.70710678118654752f));
                v01 = 0.5f * v01 * (1.0f + erff(v01 * 0.70710678118654752f));
                v10 = 0.5f * v10 * (1.0f + erff(v10 * 0.70710678118654752f));
                v11 = 0.5f * v11 * (1.0f + erff(v11 * 0.70710678118654752f));
                bf16* C = (bf16*)Cout;
                *(__nv_bfloat162*)&C[(size_t)r0 * N + col] =
                    __nv_bfloat162(__float2bfloat16(v00), __float2bfloat16(v01));
                *(__nv_bfloat162*)&C[(size_t)r1 * N + col] =
                    __nv_bfloat162(__float2bfloat16(v10), __float2bfloat16(v11));
            } else {
                float* C = (float*)Cout;
                float2 x0 = *(const float2*)&aux[(size_t)r0 * N + col];
                float2 x1v = *(const float2*)&aux[(size_t)r1 * N + col];
                *(float2*)&C[(size_t)r0 * N + col] = make_float2(v00 + x0.x,  v01 + x0.y);
                *(float2*)&C[(size_t)r1 * N + col] = make_float2(v10 + x1v.x, v11 + x1v.y);
            }
        }
    }
}

// ---------------- windowed attention (bf16 IO) ------------------------------
__device__ __forceinline__ int region3(int g) { return (g < 56) ? 0 : (g < 60 ? 1 : 2); }

__global__ void attn_kernel(const bf16* __restrict__ qkv,
                            const float* __restrict__ rpb,
                            bf16* __restrict__ o)
{
    int win  = blockIdx.x;
    int head = blockIdx.y;
    int n    = threadIdx.x;

    __shared__ float qs[NTOK][HD + 1];
    __shared__ float ks[NTOK][HD + 1];
    __shared__ float vs[NTOK][HD + 1];

    const float scale = 0.20412414523193150818f;
    size_t base = (size_t)win * NTOK * C3 + head * HD;
    for (int p = n; p < NTOK * (HD/2); p += NTOK) {
        int r = p / (HD/2), d = (p % (HD/2)) * 2;
        size_t ro = base + (size_t)r * C3 + d;
        __nv_bfloat162 q2 = *(const __nv_bfloat162*)&qkv[ro];
        __nv_bfloat162 k2 = *(const __nv_bfloat162*)&qkv[ro + CDIM];
        __nv_bfloat162 v2 = *(const __nv_bfloat162*)&qkv[ro + 2*CDIM];
        qs[r][d]   = __bfloat162float(q2.x) * scale;
        qs[r][d+1] = __bfloat162float(q2.y) * scale;
        ks[r][d]   = __bfloat162float(k2.x);
        ks[r][d+1] = __bfloat162float(k2.y);
        vs[r][d]   = __bfloat162float(v2.x);
        vs[r][d+1] = __bfloat162float(v2.y);
    }
    __syncthreads();

    float qr[HD];
    #pragma unroll
    for (int d = 0; d < HD; d++) qr[d] = qs[n][d];

    int wimg = win & 63;
    int wi = wimg >> 3, wj = wimg & 7;
    int ni = n >> 3,    nj = n & 7;
    int rn = region3(wi*8 + ni) * 3 + region3(wj*8 + nj);

    float sc[NTOK];
    float mx = -1e30f;
    #pragma unroll
    for (int m = 0; m < NTOK; m++) {
        float s = 0.0f;
        #pragma unroll
        for (int d = 0; d < HD; d++) s += qr[d] * ks[m][d];
        int mi = m >> 3, mj = m & 7;
        int rm = region3(wi*8 + mi) * 3 + region3(wj*8 + mj);
        int ridx = (ni - mi + 7) * 15 + (nj - mj + 7);
        s += rpb[ridx * NH + head];
        if (rm != rn) s -= 100.0f;
        sc[m] = s;
        mx = fmaxf(mx, s);
    }
    float sum = 0.0f;
    #pragma unroll
    for (int m = 0; m < NTOK; m++) { sc[m] = __expf(sc[m] - mx); sum += sc[m]; }
    float inv = 1.0f / sum;

    bf16* orow = o + ((size_t)win * NTOK + n) * CDIM + head * HD;
    #pragma unroll
    for (int d = 0; d < HD; d++) {
        float accv = 0.0f;
        #pragma unroll
        for (int m = 0; m < NTOK; m++) accv += sc[m] * vs[m][d];
        orow[d] = __float2bfloat16(accv * inv);
    }
}

// ---------------- launch ----------------------------------------------------
extern "C" void kernel_launch(void* const* d_in, const int* in_sizes, int n_in,
                              void* d_out, int out_size)
{
    const float* x       = (const float*)d_in[0];
    const float* norm1_g = (const float*)d_in[1];
    const float* norm1_b = (const float*)d_in[2];
    const float* qkv_w   = (const float*)d_in[3];
    const float* qkv_b   = (const float*)d_in[4];
    const float* rpb     = (const float*)d_in[5];
    const float* proj_w  = (const float*)d_in[6];
    const float* proj_b  = (const float*)d_in[7];
    const float* norm2_g = (const float*)d_in[8];
    const float* norm2_b = (const float*)d_in[9];
    const float* fc1_w   = (const float*)d_in[10];
    const float* fc1_b   = (const float*)d_in[11];
    const float* fc2_w   = (const float*)d_in[12];
    const float* fc2_b   = (const float*)d_in[13];
    float* out = (float*)d_out;

    bf16 *hw_p, *qkv_p, *o_p, *h2_p, *fc1_p;
    bf16 *wqkv_p, *wproj_p, *wfc1_p, *wfc2_p;
    float *x1_p;
    cudaGetSymbolAddress((void**)&hw_p,   g_hw);
    cudaGetSymbolAddress((void**)&qkv_p,  g_qkv);
    cudaGetSymbolAddress((void**)&o_p,    g_o);
    cudaGetSymbolAddress((void**)&x1_p,   g_x1);
    cudaGetSymbolAddress((void**)&h2_p,   g_h2);
    cudaGetSymbolAddress((void**)&fc1_p,  g_fc1);
    cudaGetSymbolAddress((void**)&wqkv_p, g_wqkv);
    cudaGetSymbolAddress((void**)&wproj_p,g_wproj);
    cudaGetSymbolAddress((void**)&wfc1_p, g_wfc1);
    cudaGetSymbolAddress((void**)&wfc2_p, g_wfc2);

    // 0) weights -> bf16
    conv_weights<<<(CH*CDIM + 255)/256, 256>>>(qkv_w, proj_w, fc1_w, fc2_w);

    // 1) LN1 + shift + window partition
    ln1_shift_window<<<TOKENS/4, 128>>>(x, norm1_g, norm1_b, hw_p);

    // 2) QKV GEMM -> bf16
    gemm_bf16<0><<<dim3(C3/96, TOKENS/128), 256>>>(hw_p, wqkv_p, qkv_b, nullptr,
                                                   qkv_p, CDIM, C3);

    // 3) windowed attention
    attn_kernel<<<dim3(NWIN, NH), NTOK>>>(qkv_p, rpb, o_p);

    // 4) proj GEMM + window-reverse + residual -> x1 (fp32)
    gemm_bf16<1><<<dim3(1, TOKENS/128), 256>>>(o_p, wproj_p, proj_b, x,
                                               x1_p, CDIM, CDIM);

    // 5) LN2 -> bf16
    ln_plain<<<TOKENS/4, 128>>>(x1_p, norm2_g, norm2_b, h2_p);

    // 6) FC1 + GELU -> bf16
    gemm_bf16<2><<<dim3(CH/96, TOKENS/128), 256>>>(h2_p, wfc1_p, fc1_b, nullptr,
                                                   fc1_p, CDIM, CH);

    // 7) FC2 + residual -> out (fp32)
    gemm_bf16<3><<<dim3(1, TOKENS/128), 256>>>(fc1_p, wfc2_p, fc2_b, x1_p,
                                               out, CH, CDIM);
}

// round 4
// speedup vs baseline: 5.2738x; 1.6572x over previous
#include <cuda_runtime.h>
#include <cuda_bf16.h>
#include <cuda_fp16.h>
#include <cstdint>
#include <cstddef>

// ---------------- static problem sizes -------------------------------------
#define B_IMG   64
#define HDIM    64
#define WDIM    64
#define WS      8
#define SS      4
#define NH      4
#define CDIM    96
#define HD      24
#define NTOK    64
#define NWIN    4096
#define TOKENS  262144
#define C3      288
#define CH      384

typedef __nv_bfloat16 bf16;

// ---------------- scratch ---------------------------------------------------
__device__ bf16  g_hw [(size_t)TOKENS * CDIM];
__device__ bf16  g_qkv[(size_t)TOKENS * C3];
__device__ bf16  g_o  [(size_t)TOKENS * CDIM];
__device__ float g_x1 [(size_t)TOKENS * CDIM];
__device__ bf16  g_h2 [(size_t)TOKENS * CDIM];
__device__ bf16  g_fc1[(size_t)TOKENS * CH];
__device__ bf16  g_wqkv[C3 * CDIM];
__device__ bf16  g_wproj[CDIM * CDIM];
__device__ bf16  g_wfc1[CH * CDIM];
__device__ bf16  g_wfc2[CDIM * CH];
__device__ float g_bias_exp[16384];   // bias * log2(e), fragment-ordered

// ---------------- asm helpers ----------------------------------------------
__device__ __forceinline__ void ldm_x4(uint32_t& r0, uint32_t& r1, uint32_t& r2,
                                       uint32_t& r3, uint32_t addr) {
    asm volatile("ldmatrix.sync.aligned.m8n8.x4.shared.b16 {%0,%1,%2,%3}, [%4];\n"
                 : "=r"(r0), "=r"(r1), "=r"(r2), "=r"(r3) : "r"(addr));
}
__device__ __forceinline__ void mma_bf16(float c[4], const uint32_t a[4],
                                         const uint32_t b[2]) {
    asm volatile(
        "mma.sync.aligned.m16n8k16.row.col.f32.bf16.bf16.f32 "
        "{%0,%1,%2,%3},{%4,%5,%6,%7},{%8,%9},{%0,%1,%2,%3};\n"
        : "+f"(c[0]), "+f"(c[1]), "+f"(c[2]), "+f"(c[3])
        : "r"(a[0]), "r"(a[1]), "r"(a[2]), "r"(a[3]), "r"(b[0]), "r"(b[1]));
}
__device__ __forceinline__ void mma_f16(float c[4], const uint32_t a[4],
                                        const uint32_t b[2]) {
    asm volatile(
        "mma.sync.aligned.m16n8k16.row.col.f32.f16.f16.f32 "
        "{%0,%1,%2,%3},{%4,%5,%6,%7},{%8,%9},{%0,%1,%2,%3};\n"
        : "+f"(c[0]), "+f"(c[1]), "+f"(c[2]), "+f"(c[3])
        : "r"(a[0]), "r"(a[1]), "r"(a[2]), "r"(a[3]), "r"(b[0]), "r"(b[1]));
}
__device__ __forceinline__ void cp16(uint32_t dst, const void* src) {
    asm volatile("cp.async.ca.shared.global [%0], [%1], 16;\n"
                 :: "r"(dst), "l"(src));
}
__device__ __forceinline__ void cp_commit() { asm volatile("cp.async.commit_group;\n"); }
__device__ __forceinline__ void cp_wait_all() { asm volatile("cp.async.wait_group 0;\n"); }

// exp2 on FFMA pipe: z in [-100, ~10]
__device__ __forceinline__ float exp2_poly(float z) {
    z = fmaxf(z, -100.0f);
    float t = z + 12582912.0f;                       // round-to-nearest magic
    int   n = __float_as_int(t) - 0x4B400000;
    float f = z - (t - 12582912.0f);                 // f in [-0.5, 0.5]
    float p = 0.009618129107f;
    p = p * f + 0.05550410866f;
    p = p * f + 0.2402265069f;
    p = p * f + 0.69314718056f;
    p = p * f + 1.0f;
    return p * __int_as_float((n + 127) << 23);
}

// ---------------- weight conversion -----------------------------------------
__global__ void conv_weights(const float* __restrict__ a, const float* __restrict__ b,
                             const float* __restrict__ c, const float* __restrict__ d)
{
    int i = blockIdx.x * 256 + threadIdx.x;
    if (i < C3 * CDIM)   g_wqkv[i]  = __float2bfloat16(a[i]);
    if (i < CDIM * CDIM) g_wproj[i] = __float2bfloat16(b[i]);
    if (i < CH * CDIM) { g_wfc1[i]  = __float2bfloat16(c[i]);
                         g_wfc2[i]  = __float2bfloat16(d[i]); }
}

// ---------------- bias expansion (fragment-ordered, x log2e) ----------------
__global__ void build_bias(const float* __restrict__ rpb)
{
    int idx = blockIdx.x * 256 + threadIdx.x;     // 16384
    int q    = idx & 3;
    int lane = (idx >> 2) & 31;
    int nt   = (idx >> 7) & 7;
    int mt   = (idx >> 10) & 1;
    int mh   = (idx >> 11) & 1;
    int head = (idx >> 12) & 3;
    int gid = lane >> 2, tig = lane & 3;
    int n = mh*32 + mt*16 + gid + ((q >> 1) << 3);
    int m = nt*8 + tig*2 + (q & 1);
    int ni = n >> 3, nj = n & 7, mi = m >> 3, mj = m & 7;
    int ridx = (ni - mi + 7) * 15 + (nj - mj + 7);
    g_bias_exp[idx] = rpb[ridx * NH + head] * 1.4426950408889634f;
}

// ---------------- LN1 + shift + window partition (bf16 out) ----------------
__global__ void ln1_shift_window(const float* __restrict__ x,
                                 const float* __restrict__ g,
                                 const float* __restrict__ b,
                                 bf16* __restrict__ out)
{
    int tok  = blockIdx.x * 4 + (threadIdx.x >> 5);
    int lane = threadIdx.x & 31;
    const float* xr = x + (size_t)tok * CDIM;
    float v0 = xr[lane*3+0], v1 = xr[lane*3+1], v2 = xr[lane*3+2];
    float s  = v0 + v1 + v2;
    float ss = v0*v0 + v1*v1 + v2*v2;
    #pragma unroll
    for (int o = 16; o; o >>= 1) {
        s  += __shfl_xor_sync(0xffffffffu, s,  o);
        ss += __shfl_xor_sync(0xffffffffu, ss, o);
    }
    float mu  = s * (1.0f/CDIM);
    float var = ss * (1.0f/CDIM) - mu*mu;
    float r   = rsqrtf(var + 1e-5f);

    int bimg = tok >> 12;
    int hw   = tok & 4095;
    int hi   = hw >> 6, wj = hw & 63;
    int i = (hi + (HDIM - SS)) & (HDIM - 1);
    int j = (wj + (WDIM - SS)) & (WDIM - 1);
    int dtok = ((bimg * 64 + (i >> 3) * 8 + (j >> 3)) << 6) + ((i & 7) << 3) + (j & 7);
    bf16* orow = out + (size_t)dtok * CDIM;
    orow[lane*3+0] = __float2bfloat16((v0 - mu) * r * g[lane*3+0] + b[lane*3+0]);
    orow[lane*3+1] = __float2bfloat16((v1 - mu) * r * g[lane*3+1] + b[lane*3+1]);
    orow[lane*3+2] = __float2bfloat16((v2 - mu) * r * g[lane*3+2] + b[lane*3+2]);
}

// ---------------- plain LN (bf16 out) ---------------------------------------
__global__ void ln_plain(const float* __restrict__ x,
                         const float* __restrict__ g,
                         const float* __restrict__ b,
                         bf16* __restrict__ out)
{
    int tok  = blockIdx.x * 4 + (threadIdx.x >> 5);
    int lane = threadIdx.x & 31;
    const float* xr = x + (size_t)tok * CDIM;
    float v0 = xr[lane*3+0], v1 = xr[lane*3+1], v2 = xr[lane*3+2];
    float s  = v0 + v1 + v2;
    float ss = v0*v0 + v1*v1 + v2*v2;
    #pragma unroll
    for (int o = 16; o; o >>= 1) {
        s  += __shfl_xor_sync(0xffffffffu, s,  o);
        ss += __shfl_xor_sync(0xffffffffu, ss, o);
    }
    float mu  = s * (1.0f/CDIM);
    float var = ss * (1.0f/CDIM) - mu*mu;
    float r   = rsqrtf(var + 1e-5f);
    bf16* orow = out + (size_t)tok * CDIM;
    orow[lane*3+0] = __float2bfloat16((v0 - mu) * r * g[lane*3+0] + b[lane*3+0]);
    orow[lane*3+1] = __float2bfloat16((v1 - mu) * r * g[lane*3+1] + b[lane*3+1]);
    orow[lane*3+2] = __float2bfloat16((v2 - mu) * r * g[lane*3+2] + b[lane*3+2]);
}

// ---------------- bf16 tensor-core GEMM (unchanged from R3) -----------------
#define SROW 40

template<int MODE>
__global__ void __launch_bounds__(256)
gemm_bf16(const bf16* __restrict__ A, const bf16* __restrict__ W,
          const float* __restrict__ bias, const float* __restrict__ aux,
          void* __restrict__ Cout, int K, int N)
{
    __shared__ bf16 As[2][128][SROW];
    __shared__ bf16 Bs[2][96][SROW];

    const int t    = threadIdx.x;
    const int bm   = blockIdx.y * 128;
    const int bn   = blockIdx.x * 96;
    const int warp = t >> 5, lane = t & 31;
    const int wrow = warp & 3;
    const int wcol = warp >> 2;
    const int gid  = lane >> 2, tig = lane & 3;

    float acc[2][6][4];
    #pragma unroll
    for (int i = 0; i < 2; i++)
        #pragma unroll
        for (int j = 0; j < 6; j++)
            #pragma unroll
            for (int q = 0; q < 4; q++) acc[i][j][q] = 0.0f;

    const int nk = K >> 5;

    auto issue = [&](int kt, int buf) {
        const int k0 = kt << 5;
        #pragma unroll
        for (int c = 0; c < 2; c++) {
            int cid = t + c * 256;
            int row = cid >> 2, cc = cid & 3;
            uint32_t dst = (uint32_t)__cvta_generic_to_shared(&As[buf][row][cc * 8]);
            cp16(dst, A + (size_t)(bm + row) * K + k0 + cc * 8);
        }
        {
            int row = t >> 2, cc = t & 3;
            uint32_t dst = (uint32_t)__cvta_generic_to_shared(&Bs[buf][row][cc * 8]);
            cp16(dst, W + (size_t)(bn + row) * K + k0 + cc * 8);
        }
        if (t < 128) {
            int cid = 256 + t;
            int row = cid >> 2, cc = cid & 3;
            uint32_t dst = (uint32_t)__cvta_generic_to_shared(&Bs[buf][row][cc * 8]);
            cp16(dst, W + (size_t)(bn + row) * K + k0 + cc * 8);
        }
        cp_commit();
    };

    issue(0, 0);

    for (int kt = 0; kt < nk; kt++) {
        cp_wait_all();
        __syncthreads();
        if (kt + 1 < nk) issue(kt + 1, (kt + 1) & 1);
        const int buf = kt & 1;

        #pragma unroll
        for (int ks = 0; ks < 32; ks += 16) {
            uint32_t af[2][4];
            #pragma unroll
            for (int mt = 0; mt < 2; mt++) {
                int row = wrow * 32 + mt * 16 + (lane & 15);
                int col = ks + ((lane >> 4) << 3);
                uint32_t addr = (uint32_t)__cvta_generic_to_shared(&As[buf][row][col]);
                ldm_x4(af[mt][0], af[mt][1], af[mt][2], af[mt][3], addr);
            }
            uint32_t bfm[6][2];
            #pragma unroll
            for (int pr = 0; pr < 3; pr++) {
                int row = wcol * 48 + pr * 16 + (lane & 7) + ((lane >> 4) << 3);
                int col = ks + (((lane >> 3) & 1) << 3);
                uint32_t addr = (uint32_t)__cvta_generic_to_shared(&Bs[buf][row][col]);
                uint32_t r0, r1, r2, r3;
                ldm_x4(r0, r1, r2, r3, addr);
                bfm[pr*2  ][0] = r0; bfm[pr*2  ][1] = r1;
                bfm[pr*2+1][0] = r2; bfm[pr*2+1][1] = r3;
            }
            #pragma unroll
            for (int mt = 0; mt < 2; mt++)
                #pragma unroll
                for (int nt = 0; nt < 6; nt++)
                    mma_bf16(acc[mt][nt], af[mt], bfm[nt]);
        }
        __syncthreads();
    }

    #pragma unroll
    for (int mt = 0; mt < 2; mt++) {
        const int r0 = bm + wrow * 32 + mt * 16 + gid;
        const int r1 = r0 + 8;
        int d0 = r0, d1 = r1;
        if (MODE == 1) {
            int w0 = (r0 >> 6) & 63, s0 = r0 & 63;
            int i0 = ((w0 >> 3) << 3) + (s0 >> 3), j0 = ((w0 & 7) << 3) + (s0 & 7);
            d0 = (r0 & ~4095) | ((((i0 + SS) & 63) << 6) | ((j0 + SS) & 63));
            int w1 = (r1 >> 6) & 63, s1 = r1 & 63;
            int i1 = ((w1 >> 3) << 3) + (s1 >> 3), j1 = ((w1 & 7) << 3) + (s1 & 7);
            d1 = (r1 & ~4095) | ((((i1 + SS) & 63) << 6) | ((j1 + SS) & 63));
        }
        #pragma unroll
        for (int nt = 0; nt < 6; nt++) {
            const int col = bn + wcol * 48 + nt * 8 + tig * 2;
            const float b0 = bias[col], b1 = bias[col + 1];
            float v00 = acc[mt][nt][0] + b0;
            float v01 = acc[mt][nt][1] + b1;
            float v10 = acc[mt][nt][2] + b0;
            float v11 = acc[mt][nt][3] + b1;
            if (MODE == 0) {
                bf16* C = (bf16*)Cout;
                *(__nv_bfloat162*)&C[(size_t)r0 * N + col] =
                    __nv_bfloat162(__float2bfloat16(v00), __float2bfloat16(v01));
                *(__nv_bfloat162*)&C[(size_t)r1 * N + col] =
                    __nv_bfloat162(__float2bfloat16(v10), __float2bfloat16(v11));
            } else if (MODE == 1) {
                float* C = (float*)Cout;
                size_t o0 = (size_t)d0 * CDIM + col;
                size_t o1 = (size_t)d1 * CDIM + col;
                float2 x0 = *(const float2*)&aux[o0];
                float2 x1v = *(const float2*)&aux[o1];
                *(float2*)&C[o0] = make_float2(v00 + x0.x,  v01 + x0.y);
                *(float2*)&C[o1] = make_float2(v10 + x1v.x, v11 + x1v.y);
            } else if (MODE == 2) {
                v00 = 0.5f * v00 * (1.0f + erff(v00 * 0.70710678118654752f));
                v01 = 0.5f * v01 * (1.0f + erff(v01 * 0.70710678118654752f));
                v10 = 0.5f * v10 * (1.0f + erff(v10 * 0.70710678118654752f));
                v11 = 0.5f * v11 * (1.0f + erff(v11 * 0.70710678118654752f));
                bf16* C = (bf16*)Cout;
                *(__nv_bfloat162*)&C[(size_t)r0 * N + col] =
                    __nv_bfloat162(__float2bfloat16(v00), __float2bfloat16(v01));
                *(__nv_bfloat162*)&C[(size_t)r1 * N + col] =
                    __nv_bfloat162(__float2bfloat16(v10), __float2bfloat16(v11));
            } else {
                float* C = (float*)Cout;
                float2 x0 = *(const float2*)&aux[(size_t)r0 * N + col];
                float2 x1v = *(const float2*)&aux[(size_t)r1 * N + col];
                *(float2*)&C[(size_t)r0 * N + col] = make_float2(v00 + x0.x,  v01 + x0.y);
                *(float2*)&C[(size_t)r1 * N + col] = make_float2(v10 + x1v.x, v11 + x1v.y);
            }
        }
    }
}

// ---------------- tensor-core windowed attention ----------------------------
// block = 1 window, 256 thr = 8 warps: warp -> (head = w>>1, query-half = w&1)
__global__ void __launch_bounds__(256)
attn_tc(const bf16* __restrict__ qkv, bf16* __restrict__ o)
{
    __shared__ __align__(16) __half Vt[NH][32][72];   // [head][d][token]

    const int win  = blockIdx.x;
    const int t    = threadIdx.x;
    const int warp = t >> 5, lane = t & 31;
    const int head = warp >> 1, mh = warp & 1;
    const int gid  = lane >> 2, tig = lane & 3;

    const bf16* wq = qkv + (size_t)win * 64 * C3;

    // ---- stage V transposed (f16), plus ones row (d=24) & zero pad rows ----
    for (int i = t; i < NH * 64 * HD; i += 256) {
        int h = i / (64 * HD), r = i % (64 * HD);
        int tok = r / HD, d = r % HD;
        Vt[h][d][tok] = __float2half(__bfloat162float(wq[tok * C3 + 192 + h * HD + d]));
    }
    {
        int h = t >> 6, tok = t & 63;
        Vt[h][24][tok] = __float2half(1.0f);
    }
    for (int i = t; i < NH * 7 * 64; i += 256) {
        int h = i / 448, r = i % 448;
        int d = 25 + r / 64, tok = r % 64;
        Vt[h][d][tok] = __float2half(0.0f);
    }
    __syncthreads();

    // ---- load Q (A-frags) and K (B-frags) directly from gmem ----
    const bf16* qb = wq + head * HD;
    const bf16* kb = wq + 96 + head * HD;

    uint32_t aq[2][2][4];
    #pragma unroll
    for (int mt = 0; mt < 2; mt++) {
        int r0 = mh * 32 + mt * 16 + gid;
        #pragma unroll
        for (int kt = 0; kt < 2; kt++) {
            int c = kt * 16 + 2 * tig;
            aq[mt][kt][0] = *(const uint32_t*)(qb + (size_t)r0 * C3 + c);
            aq[mt][kt][1] = *(const uint32_t*)(qb + (size_t)(r0 + 8) * C3 + c);
            if (kt == 0) {
                aq[mt][kt][2] = *(const uint32_t*)(qb + (size_t)r0 * C3 + c + 8);
                aq[mt][kt][3] = *(const uint32_t*)(qb + (size_t)(r0 + 8) * C3 + c + 8);
            } else { aq[mt][kt][2] = 0u; aq[mt][kt][3] = 0u; }
        }
    }
    uint32_t bk[8][2][2];
    #pragma unroll
    for (int nt = 0; nt < 8; nt++) {
        int tok = nt * 8 + gid;
        #pragma unroll
        for (int kt = 0; kt < 2; kt++) {
            int c = kt * 16 + 2 * tig;
            bk[nt][kt][0] = *(const uint32_t*)(kb + (size_t)tok * C3 + c);
            bk[nt][kt][1] = (kt == 0) ? *(const uint32_t*)(kb + (size_t)tok * C3 + c + 8) : 0u;
        }
    }

    // ---- S = Q @ K^T ----
    float acc[2][8][4];
    #pragma unroll
    for (int mt = 0; mt < 2; mt++)
        #pragma unroll
        for (int nt = 0; nt < 8; nt++)
            #pragma unroll
            for (int q = 0; q < 4; q++) acc[mt][nt][q] = 0.0f;

    #pragma unroll
    for (int mt = 0; mt < 2; mt++)
        #pragma unroll
        for (int nt = 0; nt < 8; nt++)
            #pragma unroll
            for (int kt = 0; kt < 2; kt++)
                mma_bf16(acc[mt][nt], aq[mt][kt], bk[nt][kt]);

    // ---- mask regions (window-position dependent, pure ALU) ----
    const int wimg = win & 63;
    const int wi = wimg >> 3, wj = wimg & 7;
    int rk[8];
    #pragma unroll
    for (int nt = 0; nt < 8; nt++) {
        int mrow = nt;             // key token row in window = (nt*8+2tig)>>3 = nt
        int mcol = 2 * tig;        // key token col (2tig,2tig+1 same half)
        rk[nt] = ((wi == 7) ? ((mrow < 4) ? 1 : 2) : 0) * 3
               + ((wj == 7) ? ((mcol < 4) ? 1 : 2) : 0);
    }

    const float K1 = 0.2944888985f;        // 24^-0.5 * log2(e)
    const float MASKL2 = -144.269504089f;  // -100 * log2(e)

    // ---- exp via FFMA-pipe poly, pack to f16x2 A-fragments ----
    uint32_t p01[2][8], p23[2][8];
    #pragma unroll
    for (int mt = 0; mt < 2; mt++) {
        int n0 = mh * 32 + mt * 16 + gid;
        int n1 = n0 + 8;
        int rq0 = ((wi == 7) ? (((n0 >> 3) < 4) ? 1 : 2) : 0) * 3
                + ((wj == 7) ? (((n0 & 7) < 4) ? 1 : 2) : 0);
        int rq1 = ((wi == 7) ? (((n1 >> 3) < 4) ? 1 : 2) : 0) * 3
                + ((wj == 7) ? (((n1 & 7) < 4) ? 1 : 2) : 0);
        #pragma unroll
        for (int nt = 0; nt < 8; nt++) {
            const float4 bb = *(const float4*)&g_bias_exp[
                (((((head * 2 + mh) * 2 + mt) * 8 + nt) * 32 + lane) << 2)];
            float m0 = (rq0 != rk[nt]) ? MASKL2 : 0.0f;
            float m1 = (rq1 != rk[nt]) ? MASKL2 : 0.0f;
            float e00 = exp2_poly(acc[mt][nt][0] * K1 + bb.x + m0);
            float e01 = exp2_poly(acc[mt][nt][1] * K1 + bb.y + m0);
            float e10 = exp2_poly(acc[mt][nt][2] * K1 + bb.z + m1);
            float e11 = exp2_poly(acc[mt][nt][3] * K1 + bb.w + m1);
            __half2 h01 = __floats2half2_rn(e00, e01);
            __half2 h23 = __floats2half2_rn(e10, e11);
            p01[mt][nt] = *(uint32_t*)&h01;
            p23[mt][nt] = *(uint32_t*)&h23;
        }
    }

    // ---- load V^T B-fragments from smem ----
    uint32_t bv[4][4][2];   // [d-tile][k-tile][2]
    #pragma unroll
    for (int np = 0; np < 2; np++) {
        #pragma unroll
        for (int kt = 0; kt < 4; kt++) {
            int row = np * 16 + (lane & 7) + ((lane >> 4) << 3);
            int col = kt * 16 + (((lane >> 3) & 1) << 3);
            uint32_t addr = (uint32_t)__cvta_generic_to_shared(&Vt[head][row][col]);
            uint32_t r0, r1, r2, r3;
            ldm_x4(r0, r1, r2, r3, addr);
            bv[np*2  ][kt][0] = r0; bv[np*2  ][kt][1] = r1;
            bv[np*2+1][kt][0] = r2; bv[np*2+1][kt][1] = r3;
        }
    }

    // ---- O = P @ V (col 24 = row-sum via ones row) ----
    float ao[2][4][4];
    #pragma unroll
    for (int mt = 0; mt < 2; mt++)
        #pragma unroll
        for (int nv = 0; nv < 4; nv++)
            #pragma unroll
            for (int q = 0; q < 4; q++) ao[mt][nv][q] = 0.0f;

    #pragma unroll
    for (int mt = 0; mt < 2; mt++) {
        #pragma unroll
        for (int kt = 0; kt < 4; kt++) {
            uint32_t ap[4] = { p01[mt][2*kt], p23[mt][2*kt],
                               p01[mt][2*kt+1], p23[mt][2*kt+1] };
            #pragma unroll
            for (int nv = 0; nv < 4; nv++)
                mma_f16(ao[mt][nv], ap, bv[nv][kt]);
        }
    }

    // ---- normalize & store ----
    #pragma unroll
    for (int mt = 0; mt < 2; mt++) {
        float sum0 = __shfl_sync(0xffffffffu, ao[mt][3][0], lane & 28);
        float sum1 = __shfl_sync(0xffffffffu, ao[mt][3][2], lane & 28);
        float inv0 = __fdividef(1.0f, sum0);
        float inv1 = __fdividef(1.0f, sum1);
        int row0 = win * 64 + mh * 32 + mt * 16 + gid;
        #pragma unroll
        for (int nv = 0; nv < 3; nv++) {
            int col = head * HD + nv * 8 + tig * 2;
            *(__nv_bfloat162*)&o[(size_t)row0 * CDIM + col] =
                __nv_bfloat162(__float2bfloat16(ao[mt][nv][0] * inv0),
                               __float2bfloat16(ao[mt][nv][1] * inv0));
            *(__nv_bfloat162*)&o[(size_t)(row0 + 8) * CDIM + col] =
                __nv_bfloat162(__float2bfloat16(ao[mt][nv][2] * inv1),
                               __float2bfloat16(ao[mt][nv][3] * inv1));
        }
    }
}

// ---------------- launch ----------------------------------------------------
extern "C" void kernel_launch(void* const* d_in, const int* in_sizes, int n_in,
                              void* d_out, int out_size)
{
    const float* x       = (const float*)d_in[0];
    const float* norm1_g = (const float*)d_in[1];
    const float* norm1_b = (const float*)d_in[2];
    const float* qkv_w   = (const float*)d_in[3];
    const float* qkv_b   = (const float*)d_in[4];
    const float* rpb     = (const float*)d_in[5];
    const float* proj_w  = (const float*)d_in[6];
    const float* proj_b  = (const float*)d_in[7];
    const float* norm2_g = (const float*)d_in[8];
    const float* norm2_b = (const float*)d_in[9];
    const float* fc1_w   = (const float*)d_in[10];
    const float* fc1_b   = (const float*)d_in[11];
    const float* fc2_w   = (const float*)d_in[12];
    const float* fc2_b   = (const float*)d_in[13];
    float* out = (float*)d_out;

    bf16 *hw_p, *qkv_p, *o_p, *h2_p, *fc1_p;
    bf16 *wqkv_p, *wproj_p, *wfc1_p, *wfc2_p;
    float *x1_p;
    cudaGetSymbolAddress((void**)&hw_p,   g_hw);
    cudaGetSymbolAddress((void**)&qkv_p,  g_qkv);
    cudaGetSymbolAddress((void**)&o_p,    g_o);
    cudaGetSymbolAddress((void**)&x1_p,   g_x1);
    cudaGetSymbolAddress((void**)&h2_p,   g_h2);
    cudaGetSymbolAddress((void**)&fc1_p,  g_fc1);
    cudaGetSymbolAddress((void**)&wqkv_p, g_wqkv);
    cudaGetSymbolAddress((void**)&wproj_p,g_wproj);
    cudaGetSymbolAddress((void**)&wfc1_p, g_wfc1);
    cudaGetSymbolAddress((void**)&wfc2_p, g_wfc2);

    conv_weights<<<(CH*CDIM + 255)/256, 256>>>(qkv_w, proj_w, fc1_w, fc2_w);
    build_bias<<<64, 256>>>(rpb);
    ln1_shift_window<<<TOKENS/4, 128>>>(x, norm1_g, norm1_b, hw_p);

    gemm_bf16<0><<<dim3(C3/96, TOKENS/128), 256>>>(hw_p, wqkv_p, qkv_b, nullptr,
                                                   qkv_p, CDIM, C3);

    attn_tc<<<NWIN, 256>>>(qkv_p, o_p);

    gemm_bf16<1><<<dim3(1, TOKENS/128), 256>>>(o_p, wproj_p, proj_b, x,
                                               x1_p, CDIM, CDIM);

    ln_plain<<<TOKENS/4, 128>>>(x1_p, norm2_g, norm2_b, h2_p);

    gemm_bf16<2><<<dim3(CH/96, TOKENS/128), 256>>>(h2_p, wfc1_p, fc1_b, nullptr,
                                                   fc1_p, CDIM, CH);

    gemm_bf16<3><<<dim3(1, TOKENS/128), 256>>>(fc1_p, wfc2_p, fc2_b, x1_p,
                                               out, CH, CDIM);
}